// round 7
// baseline (speedup 1.0000x reference)
#include <cuda_runtime.h>
#include <math.h>
#include <stdint.h>

// ---------------- problem constants ----------------
#define NPAIRS_MAX 200000
#define MAX_NB 6
#define TILE 32                 // pairs per block-tile
#define THREADS 256
#define NWARPS 8
#define MLP_BLOCKS 148
#define PI_F 3.14159265358979323846f

#define FEAT 322

// dynamic smem layout (floats)
#define OFF_W1   0              // [322][64] row-major
#define OFF_W2   20608          // [64][64]
#define OFF_W3   24704          // [64][64]
#define OFF_WO   28800          // [64]
#define OFF_B1   28864
#define OFF_G1   28928
#define OFF_BE1  28992
#define OFF_B2   29056
#define OFF_G2   29120
#define OFF_BE2  29184
#define OFF_B3   29248
#define OFF_G3   29312
#define OFF_BE3  29376
#define OFF_BO   29440
#define OFF_X    29444          // X[328][32]  (rows 0..321 used; 16B aligned)
#define OFF_HA   39940          // H[64][34]   (stride 34, 8B aligned)
#define OFF_HB   42116          // H[64][34]
#define SMEM_FLOATS 44292
#define SMEM_BYTES  (SMEM_FLOATS * 4)   // 177168

// ---------------- device globals ----------------
__device__ int    g_count;
__device__ int    g_done;
__device__ double g_sum;
__device__ int    g_p0[NPAIRS_MAX];
__device__ int    g_p1[NPAIRS_MAX];
__device__ float4 g_rec[NPAIRS_MAX];   // rij.x, rij.y, rij.z, w

__constant__ float c_zidx[10] = {1.f, 3.f, 5.f, 6.f, 7.f, 8.f, 9.f, 11.f, 15.f, 16.f};

// ---------------- f32x2 packed helpers ----------------
__device__ __forceinline__ unsigned long long pk2(float w) {
    unsigned long long r;
    asm("mov.b64 %0, {%1,%2};" : "=l"(r) : "f"(w), "f"(w));
    return r;
}
__device__ __forceinline__ void ffma2(unsigned long long& a, unsigned long long x,
                                      unsigned long long w) {
    asm("fma.rn.f32x2 %0, %1, %2, %0;" : "+l"(a) : "l"(x), "l"(w));
}
__device__ __forceinline__ void fadd2(unsigned long long& a, unsigned long long b) {
    asm("add.rn.f32x2 %0, %0, %1;" : "+l"(a) : "l"(b));
}

// ---------------- misc helpers ----------------
__device__ __forceinline__ void box_inverse(const float* b, float* bi) {
    float det = b[0] * (b[4] * b[8] - b[5] * b[7])
              - b[1] * (b[3] * b[8] - b[5] * b[6])
              + b[2] * (b[3] * b[7] - b[4] * b[6]);
    float id = 1.f / det;
    bi[0] = (b[4] * b[8] - b[5] * b[7]) * id;
    bi[1] = (b[2] * b[7] - b[1] * b[8]) * id;
    bi[2] = (b[1] * b[5] - b[2] * b[4]) * id;
    bi[3] = (b[5] * b[6] - b[3] * b[8]) * id;
    bi[4] = (b[0] * b[8] - b[2] * b[6]) * id;
    bi[5] = (b[2] * b[3] - b[0] * b[5]) * id;
    bi[6] = (b[3] * b[7] - b[4] * b[6]) * id;
    bi[7] = (b[1] * b[6] - b[0] * b[7]) * id;
    bi[8] = (b[0] * b[4] - b[1] * b[3]) * id;
}

__device__ __forceinline__ float3 pbc3(float dx, float dy, float dz,
                                       const float* B, const float* Bi) {
    float s0 = dx * Bi[0] + dy * Bi[3] + dz * Bi[6];
    float s1 = dx * Bi[1] + dy * Bi[4] + dz * Bi[7];
    float s2 = dx * Bi[2] + dy * Bi[5] + dz * Bi[8];
    s0 -= floorf(s0 + 0.5f);
    s1 -= floorf(s1 + 0.5f);
    s2 -= floorf(s2 + 0.5f);
    float3 r;
    r.x = s0 * B[0] + s1 * B[3] + s2 * B[6];
    r.y = s0 * B[1] + s1 * B[4] + s2 * B[7];
    r.z = s0 * B[2] + s1 * B[5] + s2 * B[8];
    return r;
}

__device__ __forceinline__ float4 allreduce4(float4 v) {
#pragma unroll
    for (int o = 16; o > 0; o >>= 1) {
        v.x += __shfl_xor_sync(0xffffffffu, v.x, o);
        v.y += __shfl_xor_sync(0xffffffffu, v.y, o);
        v.z += __shfl_xor_sync(0xffffffffu, v.z, o);
        v.w += __shfl_xor_sync(0xffffffffu, v.w, o);
    }
    return v;
}

// ---------------- block GEMM: H[64][34] = W^T X + b ----------------
// thread = (o = tid>>2 in 0..63, q = tid&3 -> pairs q*8 .. q*8+7)
// SX = row stride of X (32 for feature matrix, 34 for H buffers)
template<int SX>
__device__ __forceinline__ void gemm_tile(
    const float* __restrict__ Ws, const float* __restrict__ bb,
    const float* __restrict__ Xs, float* __restrict__ Ho,
    int inDim, int o, int q)
{
    float b = bb[o];
    unsigned long long ae0 = pk2(b), ae1 = ae0, ae2 = ae0, ae3 = ae0;
    unsigned long long ao0 = 0, ao1 = 0, ao2 = 0, ao3 = 0;
    const float* wp = Ws + o;
    const float* xp = Xs + q * 8;
#pragma unroll 2
    for (int i = 0; i < inDim; i += 2) {
        unsigned long long x0, x1, x2, x3, y0, y1, y2, y3;
        if (SX == 32) {
            ulonglong2 u0 = *(const ulonglong2*)(xp + i * 32);
            ulonglong2 u1 = *(const ulonglong2*)(xp + i * 32 + 4);
            ulonglong2 v0 = *(const ulonglong2*)(xp + (i + 1) * 32);
            ulonglong2 v1 = *(const ulonglong2*)(xp + (i + 1) * 32 + 4);
            x0 = u0.x; x1 = u0.y; x2 = u1.x; x3 = u1.y;
            y0 = v0.x; y1 = v0.y; y2 = v1.x; y3 = v1.y;
        } else {
            x0 = *(const unsigned long long*)(xp + i * SX);
            x1 = *(const unsigned long long*)(xp + i * SX + 2);
            x2 = *(const unsigned long long*)(xp + i * SX + 4);
            x3 = *(const unsigned long long*)(xp + i * SX + 6);
            y0 = *(const unsigned long long*)(xp + (i + 1) * SX);
            y1 = *(const unsigned long long*)(xp + (i + 1) * SX + 2);
            y2 = *(const unsigned long long*)(xp + (i + 1) * SX + 4);
            y3 = *(const unsigned long long*)(xp + (i + 1) * SX + 6);
        }
        unsigned long long wa = pk2(wp[i * 64]);
        unsigned long long wb = pk2(wp[(i + 1) * 64]);
        ffma2(ae0, x0, wa); ffma2(ae1, x1, wa); ffma2(ae2, x2, wa); ffma2(ae3, x3, wa);
        ffma2(ao0, y0, wb); ffma2(ao1, y1, wb); ffma2(ao2, y2, wb); ffma2(ao3, y3, wb);
    }
    fadd2(ae0, ao0); fadd2(ae1, ao1); fadd2(ae2, ao2); fadd2(ae3, ao3);
    unsigned long long* hp = (unsigned long long*)(Ho + o * 34 + q * 8);
    hp[0] = ae0; hp[1] = ae1; hp[2] = ae2; hp[3] = ae3;
}

// ---------------- warp LayerNorm over H columns (4 pairs per warp) ----------------
__device__ __forceinline__ void ln_tile(
    float* __restrict__ H, const float* __restrict__ gg, const float* __restrict__ be,
    int lane, int pbase, bool store, float4& oy0, float4& oy1)
{
    float* h0 = H + lane * 34 + pbase;
    float* h1 = H + (lane + 32) * 34 + pbase;
    float4 a0 = make_float4(h0[0], h0[1], h0[2], h0[3]);
    float4 a1 = make_float4(h1[0], h1[1], h1[2], h1[3]);
    float4 s = make_float4(a0.x + a1.x, a0.y + a1.y, a0.z + a1.z, a0.w + a1.w);
    s = allreduce4(s);
    float4 mu = make_float4(s.x * (1.f/64.f), s.y * (1.f/64.f),
                            s.z * (1.f/64.f), s.w * (1.f/64.f));
    float4 d0 = make_float4(a0.x - mu.x, a0.y - mu.y, a0.z - mu.z, a0.w - mu.w);
    float4 d1 = make_float4(a1.x - mu.x, a1.y - mu.y, a1.z - mu.z, a1.w - mu.w);
    float4 v = make_float4(d0.x*d0.x + d1.x*d1.x, d0.y*d0.y + d1.y*d1.y,
                           d0.z*d0.z + d1.z*d1.z, d0.w*d0.w + d1.w*d1.w);
    v = allreduce4(v);
    float4 r = make_float4(rsqrtf(v.x * (1.f/64.f) + 1e-6f),
                           rsqrtf(v.y * (1.f/64.f) + 1e-6f),
                           rsqrtf(v.z * (1.f/64.f) + 1e-6f),
                           rsqrtf(v.w * (1.f/64.f) + 1e-6f));
    float g0 = gg[lane], g1 = gg[lane + 32];
    float e0 = be[lane], e1 = be[lane + 32];
    float4 y0 = make_float4(fmaxf(d0.x * r.x * g0 + e0, 0.f),
                            fmaxf(d0.y * r.y * g0 + e0, 0.f),
                            fmaxf(d0.z * r.z * g0 + e0, 0.f),
                            fmaxf(d0.w * r.w * g0 + e0, 0.f));
    float4 y1 = make_float4(fmaxf(d1.x * r.x * g1 + e1, 0.f),
                            fmaxf(d1.y * r.y * g1 + e1, 0.f),
                            fmaxf(d1.z * r.z * g1 + e1, 0.f),
                            fmaxf(d1.w * r.w * g1 + e1, 0.f));
    if (store) {
        h0[0] = y0.x; h0[1] = y0.y; h0[2] = y0.z; h0[3] = y0.w;
        h1[0] = y1.x; h1[1] = y1.y; h1[2] = y1.z; h1[3] = y1.w;
    }
    oy0 = y0; oy1 = y1;
}

// ---------------- kernel 1: filter + compact ----------------
__global__ void k_filter(const float* __restrict__ pos,
                         const float* __restrict__ box,
                         const float* __restrict__ valid,
                         const int* __restrict__ pairs,
                         const int* __restrict__ molid,
                         int npairs)
{
    int i = blockIdx.x * blockDim.x + threadIdx.x;
    if (i >= npairs) return;
    int p0 = pairs[3 * i];
    int p1 = pairs[3 * i + 1];
    if (p1 - p0 <= 0) { p0 -= 1; p1 -= 2; }
    if (p0 >= p1) return;
    if (__ldg(molid + p0) == __ldg(molid + p1)) return;
    float bs = __ldg(valid + i);
    if (bs == 0.f) return;

    float B[9], Bi[9];
#pragma unroll
    for (int k = 0; k < 9; k++) B[k] = box[k];
    box_inverse(B, Bi);

    float ax = __ldg(pos + 3 * p0), ay = __ldg(pos + 3 * p0 + 1), az = __ldg(pos + 3 * p0 + 2);
    float bx = __ldg(pos + 3 * p1), by = __ldg(pos + 3 * p1 + 1), bz = __ldg(pos + 3 * p1 + 2);
    float3 r = pbc3(bx - ax, by - ay, bz - az, B, Bi);
    float cx = r.x + 1e-10f, cy = r.y + 1e-10f, cz = r.z + 1e-10f;
    float dn = sqrtf(cx * cx + cy * cy + cz * cz);
    if (dn > 5.0f) return;
    float cut = 0.5f * (1.f + __cosf(PI_F * dn * (1.f / 5.f)));
    float w = bs * cut;
    if (w <= 0.f) return;

    int slot = atomicAdd(&g_count, 1);
    g_p0[slot] = p0;
    g_p1[slot] = p1;
    g_rec[slot] = make_float4(r.x, r.y, r.z, w);
}

// ---------------- kernel 2: block-cooperative tiles of 32 pairs ----------------
__global__ __launch_bounds__(THREADS, 1)
void k_mlp(const float* __restrict__ pos,
           const float* __restrict__ box,
           const int* __restrict__ topo,
           const int* __restrict__ atype,
           const float* __restrict__ W1, const float* __restrict__ b1,
           const float* __restrict__ g1, const float* __restrict__ be1,
           const float* __restrict__ W2, const float* __restrict__ b2,
           const float* __restrict__ g2, const float* __restrict__ be2,
           const float* __restrict__ W3, const float* __restrict__ b3,
           const float* __restrict__ g3, const float* __restrict__ be3,
           const float* __restrict__ Wo, const float* __restrict__ bo,
           float* __restrict__ out)
{
    extern __shared__ float sm[];
    __shared__ int    sp0[TILE], sp1[TILE];
    __shared__ float  sux[TILE], suy[TILE], suz[TILE], swt[TILE];
    __shared__ double s_part[NWARPS];

    int tid = threadIdx.x;
    int lane = tid & 31;
    int wid = tid >> 5;
    int o = tid >> 2;       // 0..63 output index
    int q = tid & 3;        // pair octet

    // stage weights (straight row-major copies)
    {
        float4* s1 = (float4*)(sm + OFF_W1);
        const float4* w1v = (const float4*)W1;
        for (int i = tid; i < 20608 / 4; i += THREADS) s1[i] = w1v[i];
        float4* s2 = (float4*)(sm + OFF_W2);
        float4* s3 = (float4*)(sm + OFF_W3);
        const float4* w2v = (const float4*)W2;
        const float4* w3v = (const float4*)W3;
        for (int i = tid; i < 1024; i += THREADS) { s2[i] = w2v[i]; s3[i] = w3v[i]; }
        if (tid < 64) {
            sm[OFF_WO + tid] = Wo[tid];
            sm[OFF_B1 + tid] = b1[tid]; sm[OFF_G1 + tid] = g1[tid]; sm[OFF_BE1 + tid] = be1[tid];
            sm[OFF_B2 + tid] = b2[tid]; sm[OFF_G2 + tid] = g2[tid]; sm[OFF_BE2 + tid] = be2[tid];
            sm[OFF_B3 + tid] = b3[tid]; sm[OFF_G3 + tid] = g3[tid]; sm[OFF_BE3 + tid] = be3[tid];
        }
        if (tid == 0) sm[OFF_BO] = bo[0];
    }

    float B[9], Bi[9];
#pragma unroll
    for (int k = 0; k < 9; k++) B[k] = box[k];
    box_inverse(B, Bi);

    float* Xs = sm + OFF_X;
    float* HA = sm + OFF_HA;
    float* HB = sm + OFF_HB;

    int n = g_count;
    int ntiles = (n + TILE - 1) / TILE;
    double wacc = 0.0;

    __syncthreads();

    for (int tile = blockIdx.x; tile < ntiles; tile += gridDim.x) {
        // metadata for 32 pairs
        if (tid < TILE) {
            int idx = tile * TILE + tid;
            int a0 = 0, a1 = 0;
            float ux = 0.f, uy = 0.f, uz = 0.f, wv = 0.f;
            if (idx < n) {
                a0 = g_p0[idx];
                a1 = g_p1[idx];
                float4 rc = g_rec[idx];
                float cx = rc.x + 1e-10f, cy = rc.y + 1e-10f, cz = rc.z + 1e-10f;
                float r2 = cx * cx + cy * cy + cz * cz;
                float ui = rsqrtf(r2);
                float dn = r2 * ui;
                ui = 1.f / (dn + 1e-10f);
                ux = rc.x * ui; uy = rc.y * ui; uz = rc.z * ui;
                wv = rc.w;
            }
            sp0[tid] = a0; sp1[tid] = a1;
            sux[tid] = ux; suy[tid] = uy; suz[tid] = uz; swt[tid] = wv;
        }
        // zero feature matrix
        {
            float4 z4 = make_float4(0.f, 0.f, 0.f, 0.f);
            float4* xv = (float4*)Xs;
            for (int i = tid; i < (FEAT + 6) * 32 / 4; i += THREADS) xv[i] = z4;
        }
        __syncthreads();

        // one-hot / element block (thread per pair)
        if (tid < TILE) {
            int t0 = __ldg(atype + sp0[tid]);
            int t1 = __ldg(atype + sp1[tid]);
            Xs[300 * 32 + tid] = c_zidx[t0];
            Xs[(301 + t0) * 32 + tid] = 1.f;
            Xs[311 * 32 + tid] = c_zidx[t1];
            Xs[(312 + t1) * 32 + tid] = 1.f;
        }

        // edges: 384 edge slots, fully parallel; atomic scatter into Xs
        for (int e = tid; e < TILE * 12; e += THREADS) {
            int p = e / 12;
            int rr = e - p * 12;
            int side = rr >= 6;
            int m = side ? rr - 6 : rr;
            int a = side ? sp1[p] : sp0[p];
            int nb = __ldg(topo + a * MAX_NB + m);
            if (nb < 0) continue;
            float ccx = __ldg(pos + 3 * a), ccy = __ldg(pos + 3 * a + 1), ccz = __ldg(pos + 3 * a + 2);
            float ex = __ldg(pos + 3 * nb), ey = __ldg(pos + 3 * nb + 1), ez = __ldg(pos + 3 * nb + 2);
            int te = __ldg(atype + nb);
            float3 d = pbc3(ex - ccx, ey - ccy, ez - ccz, B, Bi);
            float ddx = d.x + 1e-10f, ddy = d.y + 1e-10f, ddz = d.z + 1e-10f;
            float r2 = ddx * ddx + ddy * ddy + ddz * ddz;
            float rinv = rsqrtf(r2);
            float edn = r2 * rinv;

            float fx = edn * 0.2f;
            if (fx < 1.f) {
                float ca = 0.25f * (__cosf(PI_F * fx) + 1.f);
                float* base = Xs + te * 32 + p;
#pragma unroll
                for (int k = 0; k < 20; k++) {
                    float dm = edn - (float)k * (5.f / 19.f);
                    atomicAdd(base + k * 320, ca * __expf(-100.f * dm * dm));
                }
            }
            if (nb != sp0[p] && nb != sp1[p]) {
                float sgn = side ? -1.f : 1.f;
                float cg = (d.x * sux[p] + d.y * suy[p] + d.z * suz[p]) * rinv * sgn;
                float cp = 0.5f * swt[p];
                float* base = Xs + (200 + te) * 32 + p;
#pragma unroll
                for (int k = 0; k < 10; k++) {
                    float dm = cg - (-1.f + (float)k * (2.f / 9.f));
                    atomicAdd(base + k * 320, cp * __expf(-25.f * dm * dm));
                }
            }
        }
        __syncthreads();

        // dense 1: X[322][32] -> HA
        gemm_tile<32>(sm + OFF_W1, sm + OFF_B1, Xs, HA, FEAT, o, q);
        __syncthreads();
        { float4 d0, d1; ln_tile(HA, sm + OFF_G1, sm + OFF_BE1, lane, wid * 4, true, d0, d1); }
        __syncthreads();

        // dense 2: HA -> HB
        gemm_tile<34>(sm + OFF_W2, sm + OFF_B2, HA, HB, 64, o, q);
        __syncthreads();
        { float4 d0, d1; ln_tile(HB, sm + OFF_G2, sm + OFF_BE2, lane, wid * 4, true, d0, d1); }
        __syncthreads();

        // dense 3: HB -> HA
        gemm_tile<34>(sm + OFF_W3, sm + OFF_B3, HB, HA, 64, o, q);
        __syncthreads();

        // LN3 + output layer (register path, no store)
        {
            float4 y0, y1;
            ln_tile(HA, sm + OFF_G3, sm + OFF_BE3, lane, wid * 4, false, y0, y1);
            float wo0 = sm[OFF_WO + lane], wo1 = sm[OFF_WO + lane + 32];
            float4 v = make_float4(y0.x * wo0 + y1.x * wo1,
                                   y0.y * wo0 + y1.y * wo1,
                                   y0.z * wo0 + y1.z * wo1,
                                   y0.w * wo0 + y1.w * wo1);
            v = allreduce4(v);
            if (lane == 0) {
                float bov = sm[OFF_BO];
                int pb = wid * 4;
                wacc += (double)((v.x + bov) * swt[pb]     + (v.y + bov) * swt[pb + 1]
                               + (v.z + bov) * swt[pb + 2] + (v.w + bov) * swt[pb + 3]);
            }
        }
        __syncthreads();   // protect smem reuse by next tile
    }

    // block reduction -> single global atomic
    if (lane == 0) s_part[wid] = wacc;
    __syncthreads();
    if (tid == 0) {
        double t = 0.0;
#pragma unroll
        for (int i = 0; i < NWARPS; i++) t += s_part[i];
        atomicAdd(&g_sum, t);
        __threadfence();
        int done = atomicAdd(&g_done, 1);
        if (done == (int)gridDim.x - 1) {
            double s = atomicAdd(&g_sum, 0.0);   // coherent read
            out[0] = (float)s;
            g_sum = 0.0;
            g_count = 0;
            g_done = 0;
        }
    }
}

// ---------------- launch ----------------
extern "C" void kernel_launch(void* const* d_in, const int* in_sizes, int n_in,
                              void* d_out, int out_size)
{
    const float* pos   = (const float*)d_in[0];
    const float* box   = (const float*)d_in[1];
    const float* valid = (const float*)d_in[2];
    const float* W1 = (const float*)d_in[3];
    const float* b1 = (const float*)d_in[4];
    const float* g1 = (const float*)d_in[5];
    const float* be1 = (const float*)d_in[6];
    const float* W2 = (const float*)d_in[7];
    const float* b2 = (const float*)d_in[8];
    const float* g2 = (const float*)d_in[9];
    const float* be2 = (const float*)d_in[10];
    const float* W3 = (const float*)d_in[11];
    const float* b3 = (const float*)d_in[12];
    const float* g3 = (const float*)d_in[13];
    const float* be3 = (const float*)d_in[14];
    const float* Wo = (const float*)d_in[15];
    const float* bo = (const float*)d_in[16];
    const int* pairs = (const int*)d_in[17];
    const int* topo  = (const int*)d_in[18];
    // d_in[19] topo_mask: redundant with topo != -1
    const int* molid = (const int*)d_in[20];
    const int* atype = (const int*)d_in[21];

    int npairs = in_sizes[17] / 3;
    if (npairs > NPAIRS_MAX) npairs = NPAIRS_MAX;

    cudaFuncSetAttribute(k_mlp, cudaFuncAttributeMaxDynamicSharedMemorySize, SMEM_BYTES);

    k_filter<<<(npairs + 255) / 256, 256>>>(pos, box, valid, pairs, molid, npairs);
    k_mlp<<<MLP_BLOCKS, THREADS, SMEM_BYTES>>>(pos, box, topo, atype,
        W1, b1, g1, be1, W2, b2, g2, be2, W3, b3, g3, be3, Wo, bo,
        (float*)d_out);
}

// round 9
// speedup vs baseline: 1.0052x; 1.0052x over previous
#include <cuda_runtime.h>
#include <math.h>
#include <stdint.h>

// ---------------- problem constants ----------------
#define NPAIRS_MAX 200000
#define MAX_NB 6
#define NWARPS 8
#define THREADS (NWARPS * 32)
#define PI_F 3.14159265358979323846f

#define FEAT 322
#define XROWS 328              // padded rows; each row is a float4 (4 pair slots)

// shared offsets (floats)
#define OFF_W1   0
#define OFF_W2   20608
#define OFF_W3   24704
#define OFF_WO   28800
#define OFF_B1   28864
#define OFF_G1   28928
#define OFF_BE1  28992
#define OFF_B2   29056
#define OFF_G2   29120
#define OFF_BE2  29184
#define OFF_B3   29248
#define OFF_G3   29312
#define OFF_BE3  29376
#define OFF_BO   29440
#define OFF_X    29444                              // 16B aligned
#define SMEM_FLOATS (OFF_X + NWARPS * XROWS * 4)    // 39940
#define SMEM_BYTES  (SMEM_FLOATS * 4)               // 159760 -> guarantees 1 block/SM

// ---------------- device globals ----------------
__device__ int    g_count;
__device__ int    g_bar;
__device__ int    g_done;
__device__ double g_sum;
__device__ int    g_p0[NPAIRS_MAX];
__device__ int    g_p1[NPAIRS_MAX];
__device__ float4 g_rec[NPAIRS_MAX];   // rij.x, rij.y, rij.z, w

__constant__ float c_zidx[10] = {1.f, 3.f, 5.f, 6.f, 7.f, 8.f, 9.f, 11.f, 15.f, 16.f};

// ---------------- helpers ----------------
__device__ __forceinline__ void box_inverse(const float* b, float* bi) {
    float det = b[0] * (b[4] * b[8] - b[5] * b[7])
              - b[1] * (b[3] * b[8] - b[5] * b[6])
              + b[2] * (b[3] * b[7] - b[4] * b[6]);
    float id = 1.f / det;
    bi[0] = (b[4] * b[8] - b[5] * b[7]) * id;
    bi[1] = (b[2] * b[7] - b[1] * b[8]) * id;
    bi[2] = (b[1] * b[5] - b[2] * b[4]) * id;
    bi[3] = (b[5] * b[6] - b[3] * b[8]) * id;
    bi[4] = (b[0] * b[8] - b[2] * b[6]) * id;
    bi[5] = (b[2] * b[3] - b[0] * b[5]) * id;
    bi[6] = (b[3] * b[7] - b[4] * b[6]) * id;
    bi[7] = (b[1] * b[6] - b[0] * b[7]) * id;
    bi[8] = (b[0] * b[4] - b[1] * b[3]) * id;
}

__device__ __forceinline__ float3 pbc3(float dx, float dy, float dz,
                                       const float* B, const float* Bi) {
    float s0 = dx * Bi[0] + dy * Bi[3] + dz * Bi[6];
    float s1 = dx * Bi[1] + dy * Bi[4] + dz * Bi[7];
    float s2 = dx * Bi[2] + dy * Bi[5] + dz * Bi[8];
    s0 -= floorf(s0 + 0.5f);
    s1 -= floorf(s1 + 0.5f);
    s2 -= floorf(s2 + 0.5f);
    float3 r;
    r.x = s0 * B[0] + s1 * B[3] + s2 * B[6];
    r.y = s0 * B[1] + s1 * B[4] + s2 * B[7];
    r.z = s0 * B[2] + s1 * B[5] + s2 * B[8];
    return r;
}

__device__ __forceinline__ float4 allreduce4(float4 v) {
#pragma unroll
    for (int o = 16; o > 0; o >>= 1) {
        v.x += __shfl_xor_sync(0xffffffffu, v.x, o);
        v.y += __shfl_xor_sync(0xffffffffu, v.y, o);
        v.z += __shfl_xor_sync(0xffffffffu, v.z, o);
        v.w += __shfl_xor_sync(0xffffffffu, v.w, o);
    }
    return v;
}

__device__ __forceinline__ void fma4(float4& a, const float4& x, float w) {
    a.x = fmaf(x.x, w, a.x); a.y = fmaf(x.y, w, a.y);
    a.z = fmaf(x.z, w, a.z); a.w = fmaf(x.w, w, a.w);
}
__device__ __forceinline__ float4 add4(const float4& a, const float4& b) {
    return make_float4(a.x + b.x, a.y + b.y, a.z + b.z, a.w + b.w);
}

// 4 pair-slots per warp, split accumulators (even/odd K) for ILP + shorter chains.
__device__ __forceinline__ void dense4(
    const float* __restrict__ Ws, const float* __restrict__ bb,
    const float* __restrict__ gg, const float* __restrict__ be,
    float* x, int inDim, int lane)
{
    float b0 = bb[lane], b1 = bb[lane + 32];
    float4 a0e = make_float4(b0, b0, b0, b0);
    float4 a1e = make_float4(b1, b1, b1, b1);
    float4 a0o = make_float4(0.f, 0.f, 0.f, 0.f);
    float4 a1o = make_float4(0.f, 0.f, 0.f, 0.f);
    const float* w0p = Ws + lane;
    const float* w1p = Ws + lane + 32;
#pragma unroll 2
    for (int i = 0; i < inDim; i += 2) {
        float4 xv0 = *(const float4*)(x + i * 4);
        float4 xv1 = *(const float4*)(x + (i + 1) * 4);
        float w00 = w0p[i * 64];
        float w10 = w1p[i * 64];
        float w01 = w0p[(i + 1) * 64];
        float w11 = w1p[(i + 1) * 64];
        fma4(a0e, xv0, w00); fma4(a1e, xv0, w10);
        fma4(a0o, xv1, w01); fma4(a1o, xv1, w11);
    }
    float4 a0 = add4(a0e, a0o);
    float4 a1 = add4(a1e, a1o);

    float4 s = add4(a0, a1);
    s = allreduce4(s);
    float4 mu = make_float4(s.x * (1.f/64.f), s.y * (1.f/64.f), s.z * (1.f/64.f), s.w * (1.f/64.f));
    float4 d0 = make_float4(a0.x - mu.x, a0.y - mu.y, a0.z - mu.z, a0.w - mu.w);
    float4 d1 = make_float4(a1.x - mu.x, a1.y - mu.y, a1.z - mu.z, a1.w - mu.w);
    float4 v = make_float4(d0.x*d0.x + d1.x*d1.x, d0.y*d0.y + d1.y*d1.y,
                           d0.z*d0.z + d1.z*d1.z, d0.w*d0.w + d1.w*d1.w);
    v = allreduce4(v);
    float4 r = make_float4(rsqrtf(v.x * (1.f/64.f) + 1e-6f),
                           rsqrtf(v.y * (1.f/64.f) + 1e-6f),
                           rsqrtf(v.z * (1.f/64.f) + 1e-6f),
                           rsqrtf(v.w * (1.f/64.f) + 1e-6f));
    float g0 = gg[lane], g1 = gg[lane + 32];
    float e0 = be[lane], e1 = be[lane + 32];
    float4 y0 = make_float4(fmaxf(d0.x * r.x * g0 + e0, 0.f),
                            fmaxf(d0.y * r.y * g0 + e0, 0.f),
                            fmaxf(d0.z * r.z * g0 + e0, 0.f),
                            fmaxf(d0.w * r.w * g0 + e0, 0.f));
    float4 y1 = make_float4(fmaxf(d1.x * r.x * g1 + e1, 0.f),
                            fmaxf(d1.y * r.y * g1 + e1, 0.f),
                            fmaxf(d1.z * r.z * g1 + e1, 0.f),
                            fmaxf(d1.w * r.w * g1 + e1, 0.f));
    __syncwarp();
    *(float4*)(x + lane * 4) = y0;
    *(float4*)(x + (lane + 32) * 4) = y1;
    __syncwarp();
}

// ---------------- ONE fused kernel: filter -> grid barrier -> MLP ----------------
__global__ __launch_bounds__(THREADS, 1)
void k_fused(const float* __restrict__ pos,
             const float* __restrict__ box,
             const float* __restrict__ valid,
             const int* __restrict__ pairs,
             const int* __restrict__ molid,
             const int* __restrict__ topo,
             const int* __restrict__ atype,
             const float* __restrict__ W1, const float* __restrict__ b1,
             const float* __restrict__ g1, const float* __restrict__ be1,
             const float* __restrict__ W2, const float* __restrict__ b2,
             const float* __restrict__ g2, const float* __restrict__ be2,
             const float* __restrict__ W3, const float* __restrict__ b3,
             const float* __restrict__ g3, const float* __restrict__ be3,
             const float* __restrict__ Wo, const float* __restrict__ bo,
             int npairs,
             float* __restrict__ out)
{
    extern __shared__ float sm[];
    __shared__ double s_part[NWARPS];
    int tid = threadIdx.x;
    int lane = tid & 31;
    int wid = tid >> 5;

    float B[9], Bi[9];
#pragma unroll
    for (int k = 0; k < 9; k++) B[k] = box[k];
    box_inverse(B, Bi);

    // ---------- phase 1: filter + compact (grid-strided) ----------
    for (int i = blockIdx.x * THREADS + tid; i < npairs; i += gridDim.x * THREADS) {
        int p0 = pairs[3 * i];
        int p1 = pairs[3 * i + 1];
        if (p1 - p0 <= 0) { p0 -= 1; p1 -= 2; }
        if (p0 >= p1) continue;
        if (__ldg(molid + p0) == __ldg(molid + p1)) continue;
        float bs = __ldg(valid + i);
        if (bs == 0.f) continue;

        float ax = __ldg(pos + 3 * p0), ay = __ldg(pos + 3 * p0 + 1), az = __ldg(pos + 3 * p0 + 2);
        float bx = __ldg(pos + 3 * p1), by = __ldg(pos + 3 * p1 + 1), bz = __ldg(pos + 3 * p1 + 2);
        float3 r = pbc3(bx - ax, by - ay, bz - az, B, Bi);
        float cx = r.x + 1e-10f, cy = r.y + 1e-10f, cz = r.z + 1e-10f;
        float dn = sqrtf(cx * cx + cy * cy + cz * cz);
        if (dn > 5.0f) continue;
        float cut = 0.5f * (1.f + __cosf(PI_F * dn * (1.f / 5.f)));
        float w = bs * cut;
        if (w <= 0.f) continue;

        int slot = atomicAdd(&g_count, 1);
        g_p0[slot] = p0;
        g_p1[slot] = p1;
        g_rec[slot] = make_float4(r.x, r.y, r.z, w);
    }

    // ---------- stage weights while other blocks finish filtering ----------
    {
        const float4* W1v = (const float4*)W1;
        float4* s1 = (float4*)(sm + OFF_W1);
        for (int i = tid; i < 20608 / 4; i += THREADS) s1[i] = W1v[i];
        const float4* W2v = (const float4*)W2;
        const float4* W3v = (const float4*)W3;
        float4* s2 = (float4*)(sm + OFF_W2);
        float4* s3 = (float4*)(sm + OFF_W3);
        for (int i = tid; i < 1024; i += THREADS) { s2[i] = W2v[i]; s3[i] = W3v[i]; }
        if (tid < 64) {
            sm[OFF_WO + tid] = Wo[tid];
            sm[OFF_B1 + tid] = b1[tid]; sm[OFF_G1 + tid] = g1[tid]; sm[OFF_BE1 + tid] = be1[tid];
            sm[OFF_B2 + tid] = b2[tid]; sm[OFF_G2 + tid] = g2[tid]; sm[OFF_BE2 + tid] = be2[tid];
            sm[OFF_B3 + tid] = b3[tid]; sm[OFF_G3 + tid] = g3[tid]; sm[OFF_BE3 + tid] = be3[tid];
        }
        if (tid == 0) sm[OFF_BO] = bo[0];
    }
    __syncthreads();

    // ---------- grid barrier (all blocks resident: grid == #SMs, 1 block/SM) ----------
    if (tid == 0) {
        __threadfence();
        atomicAdd(&g_bar, 1);
        while (atomicAdd(&g_bar, 0) < (int)gridDim.x) __nanosleep(64);
        __threadfence();
    }
    __syncthreads();

    // ---------- phase 2: features + MLP, 4 pairs per warp ----------
    float* x = sm + OFF_X + wid * (XROWS * 4);
    int n = g_count;
    int ngroups = (n + 3) >> 2;
    double wacc = 0.0;

    float mu_acsf = (float)lane * (5.f / 19.f);              // lanes 0..19
    float mu_apsf = -1.f + (float)(lane - 20) * (2.f / 9.f); // lanes 20..29

    for (int grp = wid * gridDim.x + blockIdx.x; grp < ngroups;
         grp += gridDim.x * NWARPS) {
        int base = grp * 4;
        int np = n - base; if (np > 4) np = 4;

        int p0s[4], p1s[4];
        float uxs[4], uys[4], uzs[4], ws[4];
#pragma unroll
        for (int s = 0; s < 4; s++) {
            if (s < np) {
                p0s[s] = g_p0[base + s];
                p1s[s] = g_p1[base + s];
                float4 rc = g_rec[base + s];
                float cx = rc.x + 1e-10f, cy = rc.y + 1e-10f, cz = rc.z + 1e-10f;
                float r2 = cx * cx + cy * cy + cz * cz;
                float ui = rsqrtf(r2);
                float dn = r2 * ui;
                ui = 1.f / (dn + 1e-10f);
                uxs[s] = rc.x * ui; uys[s] = rc.y * ui; uzs[s] = rc.z * ui;
                ws[s] = rc.w;
            } else { p0s[s] = 0; p1s[s] = 0; uxs[s] = uys[s] = uzs[s] = 0.f; ws[s] = 0.f; }
        }

        // zero feature rows
        {
            float4 z = make_float4(0.f, 0.f, 0.f, 0.f);
            float4* xv = (float4*)x;
            for (int i = lane; i < XROWS; i += 32) xv[i] = z;
        }
        __syncwarp();

        // parallel gather: lanes 0..23 fetch neighbors for slots {0,1} (A) / {2,3} (B);
        // lanes 24..31 fetch the 8 pair-atom centers.
        int nbA = -1, tA = 0, nbB = -1, tB = 0;
        float xA = 0.f, yA = 0.f, zA = 0.f, xB = 0.f, yB = 0.f, zB = 0.f;
        float cpx = 0.f, cpy = 0.f, cpz = 0.f; int cpt = 0;
        if (lane < 24) {
            int pr = lane / 12;
            int e = lane % 12;
            int side = e / 6, m = e % 6;
            if (pr < np) {
                int a = side ? p1s[pr] : p0s[pr];
                nbA = __ldg(topo + a * MAX_NB + m);
            }
            int prB = pr + 2;
            if (prB < np) {
                int a = side ? p1s[prB] : p0s[prB];
                nbB = __ldg(topo + a * MAX_NB + m);
            }
        } else {
            int k = lane - 24;
            int slot = k >> 1, which = k & 1;
            if (slot < np) {
                int a = which ? p1s[slot] : p0s[slot];
                cpx = __ldg(pos + 3 * a); cpy = __ldg(pos + 3 * a + 1); cpz = __ldg(pos + 3 * a + 2);
                cpt = __ldg(atype + a);
            }
        }
        if (lane < 24) {
            if (nbA >= 0) { xA = __ldg(pos + 3 * nbA); yA = __ldg(pos + 3 * nbA + 1); zA = __ldg(pos + 3 * nbA + 2); tA = __ldg(atype + nbA); }
            if (nbB >= 0) { xB = __ldg(pos + 3 * nbB); yB = __ldg(pos + 3 * nbB + 1); zB = __ldg(pos + 3 * nbB + 2); tB = __ldg(atype + nbB); }
        }
        __syncwarp();

        // contribution loop: 4 slots x 12 edges
#pragma unroll
        for (int slot = 0; slot < 4; slot++) {
            if (slot >= np) break;
            int t0 = __shfl_sync(0xffffffffu, cpt, 24 + slot * 2);
            int t1 = __shfl_sync(0xffffffffu, cpt, 25 + slot * 2);
            float c0x = __shfl_sync(0xffffffffu, cpx, 24 + slot * 2);
            float c0y = __shfl_sync(0xffffffffu, cpy, 24 + slot * 2);
            float c0z = __shfl_sync(0xffffffffu, cpz, 24 + slot * 2);
            float c1x = __shfl_sync(0xffffffffu, cpx, 25 + slot * 2);
            float c1y = __shfl_sync(0xffffffffu, cpy, 25 + slot * 2);
            float c1z = __shfl_sync(0xffffffffu, cpz, 25 + slot * 2);
            float ux = uxs[slot], uy = uys[slot], uz = uzs[slot];
            float cw = ws[slot];
            int q0 = p0s[slot], q1 = p1s[slot];

            if (lane == 0) {
                x[300 * 4 + slot] = c_zidx[t0];
                x[(301 + t0) * 4 + slot] = 1.f;
                x[311 * 4 + slot] = c_zidx[t1];
                x[(312 + t1) * 4 + slot] = 1.f;
            }

            for (int e = 0; e < 12; e++) {
                int srcLane = (slot & 1) * 12 + e;
                int nbe, te; float ex, ey, ez;
                if (slot < 2) {
                    nbe = __shfl_sync(0xffffffffu, nbA, srcLane);
                    ex = __shfl_sync(0xffffffffu, xA, srcLane);
                    ey = __shfl_sync(0xffffffffu, yA, srcLane);
                    ez = __shfl_sync(0xffffffffu, zA, srcLane);
                    te = __shfl_sync(0xffffffffu, tA, srcLane);
                } else {
                    nbe = __shfl_sync(0xffffffffu, nbB, srcLane);
                    ex = __shfl_sync(0xffffffffu, xB, srcLane);
                    ey = __shfl_sync(0xffffffffu, yB, srcLane);
                    ez = __shfl_sync(0xffffffffu, zB, srcLane);
                    te = __shfl_sync(0xffffffffu, tB, srcLane);
                }
                if (nbe < 0) continue;                 // uniform branch
                int side = e / 6;
                float cx = side ? c1x : c0x;
                float cy = side ? c1y : c0y;
                float cz = side ? c1z : c0z;
                float3 d = pbc3(ex - cx, ey - cy, ez - cz, B, Bi);
                float ddx = d.x + 1e-10f, ddy = d.y + 1e-10f, ddz = d.z + 1e-10f;
                float r2 = ddx * ddx + ddy * ddy + ddz * ddz;
                float rinv = rsqrtf(r2);
                float edn = r2 * rinv;

                if (lane < 20) {
                    float fx = edn * 0.2f;
                    if (fx < 1.f) {
                        float fc = 0.5f * (__cosf(PI_F * fx) + 1.f);
                        float dm = edn - mu_acsf;
                        x[(lane * 10 + te) * 4 + slot] += 0.5f * fc * __expf(-100.f * dm * dm);
                    }
                } else if (lane < 30) {
                    if (nbe != q0 && nbe != q1) {
                        float sgn = side ? -1.f : 1.f;
                        float cg = (d.x * ux + d.y * uy + d.z * uz) * rinv * sgn;
                        float dm = cg - mu_apsf;
                        x[(200 + (lane - 20) * 10 + te) * 4 + slot] +=
                            0.5f * cw * __expf(-25.f * dm * dm);
                    }
                }
            }
        }
        __syncwarp();

        dense4(sm + OFF_W1, sm + OFF_B1, sm + OFF_G1, sm + OFF_BE1, x, FEAT, lane);
        dense4(sm + OFF_W2, sm + OFF_B2, sm + OFF_G2, sm + OFF_BE2, x, 64, lane);
        dense4(sm + OFF_W3, sm + OFF_B3, sm + OFF_G3, sm + OFF_BE3, x, 64, lane);

        float wo0 = sm[OFF_WO + lane], wo1 = sm[OFF_WO + lane + 32];
        float4 xv0 = *(const float4*)(x + lane * 4);
        float4 xv1 = *(const float4*)(x + (lane + 32) * 4);
        float4 v = make_float4(xv0.x * wo0 + xv1.x * wo1,
                               xv0.y * wo0 + xv1.y * wo1,
                               xv0.z * wo0 + xv1.z * wo1,
                               xv0.w * wo0 + xv1.w * wo1);
        v = allreduce4(v);
        if (lane == 0) {
            float bov = sm[OFF_BO];
            wacc += (double)((v.x + bov) * ws[0] + (v.y + bov) * ws[1]
                           + (v.z + bov) * ws[2] + (v.w + bov) * ws[3]);
        }
    }

    // ---------- finalize: block-reduce, one global atomic, last block writes out ----------
    if (lane == 0) s_part[wid] = wacc;
    __syncthreads();
    if (tid == 0) {
        double t = 0.0;
#pragma unroll
        for (int i = 0; i < NWARPS; i++) t += s_part[i];
        atomicAdd(&g_sum, t);
        __threadfence();
        int done = atomicAdd(&g_done, 1);
        if (done == (int)gridDim.x - 1) {
            double s = atomicAdd(&g_sum, 0.0);   // coherent read
            out[0] = (float)s;
            g_sum = 0.0;
            g_count = 0;
            g_done = 0;
            g_bar = 0;
        }
    }
}

// ---------------- launch ----------------
extern "C" void kernel_launch(void* const* d_in, const int* in_sizes, int n_in,
                              void* d_out, int out_size)
{
    const float* pos   = (const float*)d_in[0];
    const float* box   = (const float*)d_in[1];
    const float* valid = (const float*)d_in[2];
    const float* W1 = (const float*)d_in[3];
    const float* b1 = (const float*)d_in[4];
    const float* g1 = (const float*)d_in[5];
    const float* be1 = (const float*)d_in[6];
    const float* W2 = (const float*)d_in[7];
    const float* b2 = (const float*)d_in[8];
    const float* g2 = (const float*)d_in[9];
    const float* be2 = (const float*)d_in[10];
    const float* W3 = (const float*)d_in[11];
    const float* b3 = (const float*)d_in[12];
    const float* g3 = (const float*)d_in[13];
    const float* be3 = (const float*)d_in[14];
    const float* Wo = (const float*)d_in[15];
    const float* bo = (const float*)d_in[16];
    const int* pairs = (const int*)d_in[17];
    const int* topo  = (const int*)d_in[18];
    // d_in[19] topo_mask: redundant with topo != -1
    const int* molid = (const int*)d_in[20];
    const int* atype = (const int*)d_in[21];

    int npairs = in_sizes[17] / 3;
    if (npairs > NPAIRS_MAX) npairs = NPAIRS_MAX;

    // grid = #SMs: with 160KB smem/block exactly one block fits per SM,
    // so all blocks are resident -> the in-kernel grid barrier cannot deadlock.
    int dev = 0, nsm = 148;
    cudaGetDevice(&dev);
    cudaDeviceGetAttribute(&nsm, cudaDevAttrMultiProcessorCount, dev);

    cudaFuncSetAttribute(k_fused, cudaFuncAttributeMaxDynamicSharedMemorySize, SMEM_BYTES);

    k_fused<<<nsm, THREADS, SMEM_BYTES>>>(pos, box, valid, pairs, molid, topo, atype,
        W1, b1, g1, be1, W2, b2, g2, be2, W3, b3, g3, be3, Wo, bo,
        npairs, (float*)d_out);
}

// round 11
// speedup vs baseline: 1.1109x; 1.1052x over previous
#include <cuda_runtime.h>
#include <math.h>
#include <stdint.h>

// ---------------- problem constants ----------------
#define NPAIRS_MAX 200000
#define MAX_NB 6
#define NWARPS 16
#define NPAIRGRP 8              // warp-pairs per block
#define THREADS (NWARPS * 32)
#define MLP_BLOCKS 148
#define PI_F 3.14159265358979323846f

#define FEAT 322
#define XROWS 328               // padded rows; each row is a float4 (4 pair slots)

// shared offsets (floats)
#define OFF_W1   0
#define OFF_W2   20608
#define OFF_W3   24704
#define OFF_WO   28800
#define OFF_B1   28864
#define OFF_G1   28928
#define OFF_BE1  28992
#define OFF_B2   29056
#define OFF_G2   29120
#define OFF_BE2  29184
#define OFF_B3   29248
#define OFF_G3   29312
#define OFF_BE3  29376
#define OFF_BO   29440
#define OFF_X    29444                                // 16B aligned
#define SMEM_FLOATS (OFF_X + NPAIRGRP * XROWS * 4)    // 39940
#define SMEM_BYTES  (SMEM_FLOATS * 4)                 // 159760 -> 1 block/SM

// ---------------- device globals ----------------
__device__ int    g_count;
__device__ int    g_done;
__device__ double g_sum;
__device__ int    g_p0[NPAIRS_MAX];
__device__ int    g_p1[NPAIRS_MAX];
__device__ float4 g_rec[NPAIRS_MAX];   // rij.x, rij.y, rij.z, w

__constant__ float c_zidx[10] = {1.f, 3.f, 5.f, 6.f, 7.f, 8.f, 9.f, 11.f, 15.f, 16.f};

// pair barrier: 2 warps = 64 threads, ids 1..8
#define PAIR_BAR(pid) asm volatile("bar.sync %0, %1;" :: "r"((pid) + 1), "r"(64) : "memory")

// ---------------- helpers ----------------
__device__ __forceinline__ void box_inverse(const float* b, float* bi) {
    float det = b[0] * (b[4] * b[8] - b[5] * b[7])
              - b[1] * (b[3] * b[8] - b[5] * b[6])
              + b[2] * (b[3] * b[7] - b[4] * b[6]);
    float id = 1.f / det;
    bi[0] = (b[4] * b[8] - b[5] * b[7]) * id;
    bi[1] = (b[2] * b[7] - b[1] * b[8]) * id;
    bi[2] = (b[1] * b[5] - b[2] * b[4]) * id;
    bi[3] = (b[5] * b[6] - b[3] * b[8]) * id;
    bi[4] = (b[0] * b[8] - b[2] * b[6]) * id;
    bi[5] = (b[2] * b[3] - b[0] * b[5]) * id;
    bi[6] = (b[3] * b[7] - b[4] * b[6]) * id;
    bi[7] = (b[1] * b[6] - b[0] * b[7]) * id;
    bi[8] = (b[0] * b[4] - b[1] * b[3]) * id;
}

__device__ __forceinline__ float3 pbc3(float dx, float dy, float dz,
                                       const float* B, const float* Bi) {
    float s0 = dx * Bi[0] + dy * Bi[3] + dz * Bi[6];
    float s1 = dx * Bi[1] + dy * Bi[4] + dz * Bi[7];
    float s2 = dx * Bi[2] + dy * Bi[5] + dz * Bi[8];
    s0 -= floorf(s0 + 0.5f);
    s1 -= floorf(s1 + 0.5f);
    s2 -= floorf(s2 + 0.5f);
    float3 r;
    r.x = s0 * B[0] + s1 * B[3] + s2 * B[6];
    r.y = s0 * B[1] + s1 * B[4] + s2 * B[7];
    r.z = s0 * B[2] + s1 * B[5] + s2 * B[8];
    return r;
}

__device__ __forceinline__ float4 allreduce4(float4 v) {
#pragma unroll
    for (int o = 16; o > 0; o >>= 1) {
        v.x += __shfl_xor_sync(0xffffffffu, v.x, o);
        v.y += __shfl_xor_sync(0xffffffffu, v.y, o);
        v.z += __shfl_xor_sync(0xffffffffu, v.z, o);
        v.w += __shfl_xor_sync(0xffffffffu, v.w, o);
    }
    return v;
}

__device__ __forceinline__ void fma4(float4& a, const float4& x, float w) {
    a.x = fmaf(x.x, w, a.x); a.y = fmaf(x.y, w, a.y);
    a.z = fmaf(x.z, w, a.z); a.w = fmaf(x.w, w, a.w);
}
__device__ __forceinline__ float4 add4(const float4& a, const float4& b) {
    return make_float4(a.x + b.x, a.y + b.y, a.z + b.z, a.w + b.w);
}

// ---------------- kernel 1: filter + compact ----------------
__global__ void k_filter(const float* __restrict__ pos,
                         const float* __restrict__ box,
                         const float* __restrict__ valid,
                         const int* __restrict__ pairs,
                         const int* __restrict__ molid,
                         int npairs)
{
    int i = blockIdx.x * blockDim.x + threadIdx.x;
    if (i >= npairs) return;
    int p0 = pairs[3 * i];
    int p1 = pairs[3 * i + 1];
    if (p1 - p0 <= 0) { p0 -= 1; p1 -= 2; }
    if (p0 >= p1) return;
    if (__ldg(molid + p0) == __ldg(molid + p1)) return;
    float bs = __ldg(valid + i);
    if (bs == 0.f) return;

    float B[9], Bi[9];
#pragma unroll
    for (int k = 0; k < 9; k++) B[k] = box[k];
    box_inverse(B, Bi);

    float ax = __ldg(pos + 3 * p0), ay = __ldg(pos + 3 * p0 + 1), az = __ldg(pos + 3 * p0 + 2);
    float bx = __ldg(pos + 3 * p1), by = __ldg(pos + 3 * p1 + 1), bz = __ldg(pos + 3 * p1 + 2);
    float3 r = pbc3(bx - ax, by - ay, bz - az, B, Bi);
    float cx = r.x + 1e-10f, cy = r.y + 1e-10f, cz = r.z + 1e-10f;
    float dn = sqrtf(cx * cx + cy * cy + cz * cz);
    if (dn > 5.0f) return;
    float cut = 0.5f * (1.f + __cosf(PI_F * dn * (1.f / 5.f)));
    float w = bs * cut;
    if (w <= 0.f) return;

    int slot = atomicAdd(&g_count, 1);
    g_p0[slot] = p0;
    g_p1[slot] = p1;
    g_rec[slot] = make_float4(r.x, r.y, r.z, w);
}

// ---------------- kernel 2: warp-PAIR per 4-pair group ----------------
__global__ __launch_bounds__(THREADS, 1)
void k_mlp(const float* __restrict__ pos,
           const float* __restrict__ box,
           const int* __restrict__ topo,
           const int* __restrict__ atype,
           const float* __restrict__ W1, const float* __restrict__ b1,
           const float* __restrict__ g1, const float* __restrict__ be1,
           const float* __restrict__ W2, const float* __restrict__ b2,
           const float* __restrict__ g2, const float* __restrict__ be2,
           const float* __restrict__ W3, const float* __restrict__ b3,
           const float* __restrict__ g3, const float* __restrict__ be3,
           const float* __restrict__ Wo, const float* __restrict__ bo,
           float* __restrict__ out)
{
    extern __shared__ float sm[];
    __shared__ float4 s_red[NPAIRGRP][2];   // LN sum/var + output exchange
    __shared__ double s_part[NWARPS];

    int tid = threadIdx.x;
    int lane = tid & 31;
    int wid = tid >> 5;
    int pidx = wid >> 1;        // warp-pair id 0..7
    int half = wid & 1;         // output half

    // ---- stage weights ----
    {
        const float4* W1v = (const float4*)W1;
        float4* s1 = (float4*)(sm + OFF_W1);
        for (int i = tid; i < 20608 / 4; i += THREADS) s1[i] = W1v[i];
        const float4* W2v = (const float4*)W2;
        const float4* W3v = (const float4*)W3;
        float4* s2 = (float4*)(sm + OFF_W2);
        float4* s3 = (float4*)(sm + OFF_W3);
        for (int i = tid; i < 1024; i += THREADS) { s2[i] = W2v[i]; s3[i] = W3v[i]; }
        if (tid < 64) {
            sm[OFF_WO + tid] = Wo[tid];
            sm[OFF_B1 + tid] = b1[tid]; sm[OFF_G1 + tid] = g1[tid]; sm[OFF_BE1 + tid] = be1[tid];
            sm[OFF_B2 + tid] = b2[tid]; sm[OFF_G2 + tid] = g2[tid]; sm[OFF_BE2 + tid] = be2[tid];
            sm[OFF_B3 + tid] = b3[tid]; sm[OFF_G3 + tid] = g3[tid]; sm[OFF_BE3 + tid] = be3[tid];
        }
        if (tid == 0) sm[OFF_BO] = bo[0];
    }
    __syncthreads();

    float B[9], Bi[9];
#pragma unroll
    for (int k = 0; k < 9; k++) B[k] = box[k];
    box_inverse(B, Bi);

    float* x = sm + OFF_X + pidx * (XROWS * 4);
    int o = half * 32 + lane;                 // this thread's output index
    int n = g_count;
    int ngroups = (n + 3) >> 2;
    double wacc = 0.0;

    float mu_acsf = (float)lane * (5.f / 19.f);              // lanes 0..19
    float mu_apsf = -1.f + (float)(lane - 20) * (2.f / 9.f); // lanes 20..29

    for (int grp = pidx * gridDim.x + blockIdx.x; grp < ngroups;
         grp += gridDim.x * NPAIRGRP) {
        int base = grp * 4;
        int np = n - base; if (np > 4) np = 4;
        int npw = np - half * 2;              // this warp's local slot count
        if (npw < 0) npw = 0; if (npw > 2) npw = 2;

        // this warp's 2 slots (global slots half*2, half*2+1)
        int p0s[2], p1s[2];
        float uxs[2], uys[2], uzs[2], ws2[2];
#pragma unroll
        for (int s = 0; s < 2; s++) {
            if (s < npw) {
                int idx = base + half * 2 + s;
                p0s[s] = g_p0[idx];
                p1s[s] = g_p1[idx];
                float4 rc = g_rec[idx];
                float cx = rc.x + 1e-10f, cy = rc.y + 1e-10f, cz = rc.z + 1e-10f;
                float r2 = cx * cx + cy * cy + cz * cz;
                float ui = rsqrtf(r2);
                float dn = r2 * ui;
                ui = 1.f / (dn + 1e-10f);
                uxs[s] = rc.x * ui; uys[s] = rc.y * ui; uzs[s] = rc.z * ui;
                ws2[s] = rc.w;
            } else { p0s[s] = 0; p1s[s] = 0; uxs[s] = uys[s] = uzs[s] = 0.f; ws2[s] = 0.f; }
        }

        // zero this warp's half of the feature rows
        {
            float4 z = make_float4(0.f, 0.f, 0.f, 0.f);
            float4* xv = (float4*)x;
            for (int i = half * (XROWS / 2) + lane; i < (half + 1) * (XROWS / 2); i += 32)
                xv[i] = z;
        }
        PAIR_BAR(pidx);

        // gathers: lanes 0..23 -> 24 edges (2 slots x 12); lanes 24..27 -> centers
        int nbL = -1, tL = 0;
        float nxL = 0.f, nyL = 0.f, nzL = 0.f;
        float cpx = 0.f, cpy = 0.f, cpz = 0.f; int cpt = 0;
        if (lane < 24) {
            int sl = lane / 12;
            int e = lane % 12;
            int side = e / 6, m = e % 6;
            if (sl < npw) {
                int a = side ? p1s[sl] : p0s[sl];
                nbL = __ldg(topo + a * MAX_NB + m);
                if (nbL >= 0) {
                    nxL = __ldg(pos + 3 * nbL);
                    nyL = __ldg(pos + 3 * nbL + 1);
                    nzL = __ldg(pos + 3 * nbL + 2);
                    tL = __ldg(atype + nbL);
                }
            }
        } else if (lane < 28) {
            int k = lane - 24;
            int sl = k >> 1, which = k & 1;
            if (sl < npw) {
                int a = which ? p1s[sl] : p0s[sl];
                cpx = __ldg(pos + 3 * a); cpy = __ldg(pos + 3 * a + 1); cpz = __ldg(pos + 3 * a + 2);
                cpt = __ldg(atype + a);
            }
        }
        __syncwarp();

        // one-hot block (lane s writes its slot)
#pragma unroll
        for (int s = 0; s < 2; s++) {
            int t0 = __shfl_sync(0xffffffffu, cpt, 24 + s * 2);
            int t1 = __shfl_sync(0xffffffffu, cpt, 25 + s * 2);
            if (lane == s && s < npw) {
                int gslot = half * 2 + s;
                x[300 * 4 + gslot] = c_zidx[t0];
                x[(301 + t0) * 4 + gslot] = 1.f;
                x[311 * 4 + gslot] = c_zidx[t1];
                x[(312 + t1) * 4 + gslot] = 1.f;
            }
        }

        // 24-edge contribution loop
        for (int e = 0; e < 24; e++) {
            int nbe = __shfl_sync(0xffffffffu, nbL, e);
            float ex = __shfl_sync(0xffffffffu, nxL, e);
            float ey = __shfl_sync(0xffffffffu, nyL, e);
            float ez = __shfl_sync(0xffffffffu, nzL, e);
            int te = __shfl_sync(0xffffffffu, tL, e);
            int sl = e / 12;
            int side = (e % 12) / 6;
            int srcC = 24 + sl * 2 + side;
            float cx = __shfl_sync(0xffffffffu, cpx, srcC);
            float cy = __shfl_sync(0xffffffffu, cpy, srcC);
            float cz = __shfl_sync(0xffffffffu, cpz, srcC);
            if (nbe < 0) continue;                 // uniform
            int gslot = half * 2 + sl;

            float3 d = pbc3(ex - cx, ey - cy, ez - cz, B, Bi);
            float ddx = d.x + 1e-10f, ddy = d.y + 1e-10f, ddz = d.z + 1e-10f;
            float r2 = ddx * ddx + ddy * ddy + ddz * ddz;
            float rinv = rsqrtf(r2);
            float edn = r2 * rinv;

            if (lane < 20) {
                float fx = edn * 0.2f;
                if (fx < 1.f) {
                    float fc = 0.5f * (__cosf(PI_F * fx) + 1.f);
                    float dm = edn - mu_acsf;
                    x[(lane * 10 + te) * 4 + gslot] += 0.5f * fc * __expf(-100.f * dm * dm);
                }
            } else if (lane < 30) {
                if (nbe != p0s[sl] && nbe != p1s[sl]) {
                    float sgn = side ? -1.f : 1.f;
                    float cg = (d.x * uxs[sl] + d.y * uys[sl] + d.z * uzs[sl]) * rinv * sgn;
                    float dm = cg - mu_apsf;
                    x[(200 + (lane - 20) * 10 + te) * 4 + gslot] +=
                        0.5f * ws2[sl] * __expf(-25.f * dm * dm);
                }
            }
        }
        PAIR_BAR(pidx);

        // ---- 3 dense layers, outputs split across the warp pair ----
        float4 y;
#pragma unroll
        for (int layer = 0; layer < 3; layer++) {
            const float* Ws = sm + (layer == 0 ? OFF_W1 : (layer == 1 ? OFF_W2 : OFF_W3));
            const float* bb = sm + (layer == 0 ? OFF_B1 : (layer == 1 ? OFF_B2 : OFF_B3));
            const float* gg = sm + (layer == 0 ? OFF_G1 : (layer == 1 ? OFF_G2 : OFF_G3));
            const float* be = sm + (layer == 0 ? OFF_BE1 : (layer == 1 ? OFF_BE2 : OFF_BE3));
            int inDim = (layer == 0) ? FEAT : 64;

            float bv = bb[o];
            float4 ae = make_float4(bv, bv, bv, bv);
            float4 ao = make_float4(0.f, 0.f, 0.f, 0.f);
            const float* wp = Ws + o;
#pragma unroll 4
            for (int i = 0; i < inDim; i += 2) {
                float4 x0 = *(const float4*)(x + i * 4);
                float4 x1 = *(const float4*)(x + (i + 1) * 4);
                float w0 = wp[i * 64];
                float w1 = wp[(i + 1) * 64];
                fma4(ae, x0, w0);
                fma4(ao, x1, w1);
            }
            float4 a = add4(ae, ao);

            // LayerNorm across the warp pair
            float4 s = allreduce4(a);
            if (lane == 0) s_red[pidx][half] = s;
            PAIR_BAR(pidx);
            s = add4(s, s_red[pidx][half ^ 1]);
            float4 mu = make_float4(s.x * (1.f/64.f), s.y * (1.f/64.f),
                                    s.z * (1.f/64.f), s.w * (1.f/64.f));
            float4 d = make_float4(a.x - mu.x, a.y - mu.y, a.z - mu.z, a.w - mu.w);
            float4 v = allreduce4(make_float4(d.x*d.x, d.y*d.y, d.z*d.z, d.w*d.w));
            PAIR_BAR(pidx);                  // WAR: partner read s_red[sum] done
            if (lane == 0) s_red[pidx][half] = v;
            PAIR_BAR(pidx);
            v = add4(v, s_red[pidx][half ^ 1]);
            float4 r = make_float4(rsqrtf(v.x * (1.f/64.f) + 1e-6f),
                                   rsqrtf(v.y * (1.f/64.f) + 1e-6f),
                                   rsqrtf(v.z * (1.f/64.f) + 1e-6f),
                                   rsqrtf(v.w * (1.f/64.f) + 1e-6f));
            float gv = gg[o], ev = be[o];
            y = make_float4(fmaxf(d.x * r.x * gv + ev, 0.f),
                            fmaxf(d.y * r.y * gv + ev, 0.f),
                            fmaxf(d.z * r.z * gv + ev, 0.f),
                            fmaxf(d.w * r.w * gv + ev, 0.f));
            if (layer < 2) {
                PAIR_BAR(pidx);              // WAR: partner read s_red[var] done
                *(float4*)(x + o * 4) = y;   // row o: disjoint between halves
                PAIR_BAR(pidx);              // X complete before next layer reads
            }
        }

        // ---- output layer ----
        {
            float wo = sm[OFF_WO + o];
            float4 v = make_float4(y.x * wo, y.y * wo, y.z * wo, y.w * wo);
            v = allreduce4(v);
            PAIR_BAR(pidx);                  // WAR on s_red from LN3
            if (lane == 0) s_red[pidx][half] = v;
            PAIR_BAR(pidx);
            v = add4(v, s_red[pidx][half ^ 1]);
            if (lane == 0) {
                float bov = sm[OFF_BO];
                // each warp applies weights for ITS two slots
                float c0 = half ? v.z : v.x;
                float c1 = half ? v.w : v.y;
                wacc += (double)((c0 + bov) * ws2[0] + (c1 + bov) * ws2[1]);
            }
            PAIR_BAR(pidx);                  // protect s_red reuse next group
        }
    }

    // ---- finalize: block-reduce, one global atomic, last block writes out ----
    if (lane == 0) s_part[wid] = wacc;
    __syncthreads();
    if (tid == 0) {
        double t = 0.0;
#pragma unroll
        for (int i = 0; i < NWARPS; i++) t += s_part[i];
        atomicAdd(&g_sum, t);
        __threadfence();
        int done = atomicAdd(&g_done, 1);
        if (done == (int)gridDim.x - 1) {
            double s = atomicAdd(&g_sum, 0.0);   // coherent read
            out[0] = (float)s;
            g_sum = 0.0;
            g_count = 0;
            g_done = 0;
        }
    }
}

// ---------------- launch ----------------
extern "C" void kernel_launch(void* const* d_in, const int* in_sizes, int n_in,
                              void* d_out, int out_size)
{
    const float* pos   = (const float*)d_in[0];
    const float* box   = (const float*)d_in[1];
    const float* valid = (const float*)d_in[2];
    const float* W1 = (const float*)d_in[3];
    const float* b1 = (const float*)d_in[4];
    const float* g1 = (const float*)d_in[5];
    const float* be1 = (const float*)d_in[6];
    const float* W2 = (const float*)d_in[7];
    const float* b2 = (const float*)d_in[8];
    const float* g2 = (const float*)d_in[9];
    const float* be2 = (const float*)d_in[10];
    const float* W3 = (const float*)d_in[11];
    const float* b3 = (const float*)d_in[12];
    const float* g3 = (const float*)d_in[13];
    const float* be3 = (const float*)d_in[14];
    const float* Wo = (const float*)d_in[15];
    const float* bo = (const float*)d_in[16];
    const int* pairs = (const int*)d_in[17];
    const int* topo  = (const int*)d_in[18];
    // d_in[19] topo_mask: redundant with topo != -1
    const int* molid = (const int*)d_in[20];
    const int* atype = (const int*)d_in[21];

    int npairs = in_sizes[17] / 3;
    if (npairs > NPAIRS_MAX) npairs = NPAIRS_MAX;

    cudaFuncSetAttribute(k_mlp, cudaFuncAttributeMaxDynamicSharedMemorySize, SMEM_BYTES);

    k_filter<<<(npairs + 255) / 256, 256>>>(pos, box, valid, pairs, molid, npairs);
    k_mlp<<<MLP_BLOCKS, THREADS, SMEM_BYTES>>>(pos, box, topo, atype,
        W1, b1, g1, be1, W2, b2, g2, be2, W3, b3, g3, be3, Wo, bo,
        (float*)d_out);
}

// round 12
// speedup vs baseline: 1.1726x; 1.0555x over previous
#include <cuda_runtime.h>
#include <math.h>
#include <stdint.h>

// ---------------- problem constants ----------------
#define NPAIRS_MAX 200000
#define MAX_NB 6
#define NWARPS 8
#define THREADS (NWARPS * 32)
#define MLP_BLOCKS 148
#define PI_F 3.14159265358979323846f

#define FEAT 322
#define XROWS 328              // padded rows; each row is a float4 (4 pair slots)

// shared offsets (floats)
#define OFF_W1   0
#define OFF_W2   20608
#define OFF_W3   24704
#define OFF_WO   28800
#define OFF_B1   28864
#define OFF_G1   28928
#define OFF_BE1  28992
#define OFF_B2   29056
#define OFF_G2   29120
#define OFF_BE2  29184
#define OFF_B3   29248
#define OFF_G3   29312
#define OFF_BE3  29376
#define OFF_BO   29440
#define OFF_X    29444                              // 16B aligned
#define SMEM_FLOATS (OFF_X + NWARPS * XROWS * 4)    // 39940
#define SMEM_BYTES  (SMEM_FLOATS * 4)               // 159760 -> 1 block/SM

// ---------------- device globals ----------------
__device__ int    g_count;
__device__ int    g_done;
__device__ double g_sum;
__device__ int    g_p0[NPAIRS_MAX];
__device__ int    g_p1[NPAIRS_MAX];
__device__ float4 g_rec[NPAIRS_MAX];   // rij.x, rij.y, rij.z, w

__constant__ float c_zidx[10] = {1.f, 3.f, 5.f, 6.f, 7.f, 8.f, 9.f, 11.f, 15.f, 16.f};

// ---------------- helpers ----------------
__device__ __forceinline__ void box_inverse(const float* b, float* bi) {
    float det = b[0] * (b[4] * b[8] - b[5] * b[7])
              - b[1] * (b[3] * b[8] - b[5] * b[6])
              + b[2] * (b[3] * b[7] - b[4] * b[6]);
    float id = 1.f / det;
    bi[0] = (b[4] * b[8] - b[5] * b[7]) * id;
    bi[1] = (b[2] * b[7] - b[1] * b[8]) * id;
    bi[2] = (b[1] * b[5] - b[2] * b[4]) * id;
    bi[3] = (b[5] * b[6] - b[3] * b[8]) * id;
    bi[4] = (b[0] * b[8] - b[2] * b[6]) * id;
    bi[5] = (b[2] * b[3] - b[0] * b[5]) * id;
    bi[6] = (b[3] * b[7] - b[4] * b[6]) * id;
    bi[7] = (b[1] * b[6] - b[0] * b[7]) * id;
    bi[8] = (b[0] * b[4] - b[1] * b[3]) * id;
}

__device__ __forceinline__ float3 pbc3(float dx, float dy, float dz,
                                       const float* B, const float* Bi) {
    float s0 = dx * Bi[0] + dy * Bi[3] + dz * Bi[6];
    float s1 = dx * Bi[1] + dy * Bi[4] + dz * Bi[7];
    float s2 = dx * Bi[2] + dy * Bi[5] + dz * Bi[8];
    s0 -= floorf(s0 + 0.5f);
    s1 -= floorf(s1 + 0.5f);
    s2 -= floorf(s2 + 0.5f);
    float3 r;
    r.x = s0 * B[0] + s1 * B[3] + s2 * B[6];
    r.y = s0 * B[1] + s1 * B[4] + s2 * B[7];
    r.z = s0 * B[2] + s1 * B[5] + s2 * B[8];
    return r;
}

__device__ __forceinline__ float4 allreduce4(float4 v) {
#pragma unroll
    for (int o = 16; o > 0; o >>= 1) {
        v.x += __shfl_xor_sync(0xffffffffu, v.x, o);
        v.y += __shfl_xor_sync(0xffffffffu, v.y, o);
        v.z += __shfl_xor_sync(0xffffffffu, v.z, o);
        v.w += __shfl_xor_sync(0xffffffffu, v.w, o);
    }
    return v;
}

__device__ __forceinline__ void fma4(float4& a, const float4& x, float w) {
    a.x = fmaf(x.x, w, a.x); a.y = fmaf(x.y, w, a.y);
    a.z = fmaf(x.z, w, a.z); a.w = fmaf(x.w, w, a.w);
}
__device__ __forceinline__ float4 add4(const float4& a, const float4& b) {
    return make_float4(a.x + b.x, a.y + b.y, a.z + b.z, a.w + b.w);
}

// 4 pair-slots per warp, software-pipelined: 4-row blocks, all loads hoisted
// before the 32 FMAs so LDS latency hides under the FMA stream.
// Accumulation order per accumulator is IDENTICAL to the R5 kernel (bit-exact).
__device__ __forceinline__ void dense4(
    const float* __restrict__ Ws, const float* __restrict__ bb,
    const float* __restrict__ gg, const float* __restrict__ be,
    float* x, int inDim, int lane)
{
    float b0 = bb[lane], b1 = bb[lane + 32];
    float4 a0e = make_float4(b0, b0, b0, b0);
    float4 a1e = make_float4(b1, b1, b1, b1);
    float4 a0o = make_float4(0.f, 0.f, 0.f, 0.f);
    float4 a1o = make_float4(0.f, 0.f, 0.f, 0.f);
    const float* w0p = Ws + lane;
    const float* w1p = Ws + lane + 32;
    int nBlk = inDim & ~3;
#pragma unroll 2
    for (int i = 0; i < nBlk; i += 4) {
        float4 xv0 = *(const float4*)(x + i * 4);
        float4 xv1 = *(const float4*)(x + (i + 1) * 4);
        float4 xv2 = *(const float4*)(x + (i + 2) * 4);
        float4 xv3 = *(const float4*)(x + (i + 3) * 4);
        float w00 = w0p[i * 64],       w10 = w1p[i * 64];
        float w01 = w0p[(i + 1) * 64], w11 = w1p[(i + 1) * 64];
        float w02 = w0p[(i + 2) * 64], w12 = w1p[(i + 2) * 64];
        float w03 = w0p[(i + 3) * 64], w13 = w1p[(i + 3) * 64];
        fma4(a0e, xv0, w00); fma4(a1e, xv0, w10);
        fma4(a0o, xv1, w01); fma4(a1o, xv1, w11);
        fma4(a0e, xv2, w02); fma4(a1e, xv2, w12);
        fma4(a0o, xv3, w03); fma4(a1o, xv3, w13);
    }
    if (inDim & 2) {                       // tail 2 rows (inDim = 322)
        int i = nBlk;
        float4 xv0 = *(const float4*)(x + i * 4);
        float4 xv1 = *(const float4*)(x + (i + 1) * 4);
        float w00 = w0p[i * 64],       w10 = w1p[i * 64];
        float w01 = w0p[(i + 1) * 64], w11 = w1p[(i + 1) * 64];
        fma4(a0e, xv0, w00); fma4(a1e, xv0, w10);
        fma4(a0o, xv1, w01); fma4(a1o, xv1, w11);
    }
    float4 a0 = add4(a0e, a0o);
    float4 a1 = add4(a1e, a1o);

    float4 s = add4(a0, a1);
    s = allreduce4(s);
    float4 mu = make_float4(s.x * (1.f/64.f), s.y * (1.f/64.f), s.z * (1.f/64.f), s.w * (1.f/64.f));
    float4 d0 = make_float4(a0.x - mu.x, a0.y - mu.y, a0.z - mu.z, a0.w - mu.w);
    float4 d1 = make_float4(a1.x - mu.x, a1.y - mu.y, a1.z - mu.z, a1.w - mu.w);
    float4 v = make_float4(d0.x*d0.x + d1.x*d1.x, d0.y*d0.y + d1.y*d1.y,
                           d0.z*d0.z + d1.z*d1.z, d0.w*d0.w + d1.w*d1.w);
    v = allreduce4(v);
    float4 r = make_float4(rsqrtf(v.x * (1.f/64.f) + 1e-6f),
                           rsqrtf(v.y * (1.f/64.f) + 1e-6f),
                           rsqrtf(v.z * (1.f/64.f) + 1e-6f),
                           rsqrtf(v.w * (1.f/64.f) + 1e-6f));
    float g0 = gg[lane], g1 = gg[lane + 32];
    float e0 = be[lane], e1 = be[lane + 32];
    float4 y0 = make_float4(fmaxf(d0.x * r.x * g0 + e0, 0.f),
                            fmaxf(d0.y * r.y * g0 + e0, 0.f),
                            fmaxf(d0.z * r.z * g0 + e0, 0.f),
                            fmaxf(d0.w * r.w * g0 + e0, 0.f));
    float4 y1 = make_float4(fmaxf(d1.x * r.x * g1 + e1, 0.f),
                            fmaxf(d1.y * r.y * g1 + e1, 0.f),
                            fmaxf(d1.z * r.z * g1 + e1, 0.f),
                            fmaxf(d1.w * r.w * g1 + e1, 0.f));
    __syncwarp();
    *(float4*)(x + lane * 4) = y0;
    *(float4*)(x + (lane + 32) * 4) = y1;
    __syncwarp();
}

// ---------------- kernel 1: filter + compact ----------------
__global__ void k_filter(const float* __restrict__ pos,
                         const float* __restrict__ box,
                         const float* __restrict__ valid,
                         const int* __restrict__ pairs,
                         const int* __restrict__ molid,
                         int npairs)
{
    int i = blockIdx.x * blockDim.x + threadIdx.x;
    if (i >= npairs) return;
    int p0 = pairs[3 * i];
    int p1 = pairs[3 * i + 1];
    if (p1 - p0 <= 0) { p0 -= 1; p1 -= 2; }
    if (p0 >= p1) return;
    if (__ldg(molid + p0) == __ldg(molid + p1)) return;
    float bs = __ldg(valid + i);
    if (bs == 0.f) return;

    float B[9], Bi[9];
#pragma unroll
    for (int k = 0; k < 9; k++) B[k] = box[k];
    box_inverse(B, Bi);

    float ax = __ldg(pos + 3 * p0), ay = __ldg(pos + 3 * p0 + 1), az = __ldg(pos + 3 * p0 + 2);
    float bx = __ldg(pos + 3 * p1), by = __ldg(pos + 3 * p1 + 1), bz = __ldg(pos + 3 * p1 + 2);
    float3 r = pbc3(bx - ax, by - ay, bz - az, B, Bi);
    float cx = r.x + 1e-10f, cy = r.y + 1e-10f, cz = r.z + 1e-10f;
    float dn = sqrtf(cx * cx + cy * cy + cz * cz);
    if (dn > 5.0f) return;
    float cut = 0.5f * (1.f + __cosf(PI_F * dn * (1.f / 5.f)));
    float w = bs * cut;
    if (w <= 0.f) return;

    int slot = atomicAdd(&g_count, 1);
    g_p0[slot] = p0;
    g_p1[slot] = p1;
    g_rec[slot] = make_float4(r.x, r.y, r.z, w);
}

// ---------------- kernel 2: features + MLP, 4 pairs per warp ----------------
__global__ __launch_bounds__(THREADS, 1)
void k_mlp(const float* __restrict__ pos,
           const float* __restrict__ box,
           const int* __restrict__ topo,
           const int* __restrict__ atype,
           const float* __restrict__ W1, const float* __restrict__ b1,
           const float* __restrict__ g1, const float* __restrict__ be1,
           const float* __restrict__ W2, const float* __restrict__ b2,
           const float* __restrict__ g2, const float* __restrict__ be2,
           const float* __restrict__ W3, const float* __restrict__ b3,
           const float* __restrict__ g3, const float* __restrict__ be3,
           const float* __restrict__ Wo, const float* __restrict__ bo,
           float* __restrict__ out)
{
    extern __shared__ float sm[];
    __shared__ double s_part[NWARPS];
    int tid = threadIdx.x;

    // stage weights (float4 copies)
    {
        const float4* W1v = (const float4*)W1;
        float4* s1 = (float4*)(sm + OFF_W1);
        for (int i = tid; i < 20608 / 4; i += THREADS) s1[i] = W1v[i];
        const float4* W2v = (const float4*)W2;
        const float4* W3v = (const float4*)W3;
        float4* s2 = (float4*)(sm + OFF_W2);
        float4* s3 = (float4*)(sm + OFF_W3);
        for (int i = tid; i < 1024; i += THREADS) { s2[i] = W2v[i]; s3[i] = W3v[i]; }
        if (tid < 64) {
            sm[OFF_WO + tid] = Wo[tid];
            sm[OFF_B1 + tid] = b1[tid]; sm[OFF_G1 + tid] = g1[tid]; sm[OFF_BE1 + tid] = be1[tid];
            sm[OFF_B2 + tid] = b2[tid]; sm[OFF_G2 + tid] = g2[tid]; sm[OFF_BE2 + tid] = be2[tid];
            sm[OFF_B3 + tid] = b3[tid]; sm[OFF_G3 + tid] = g3[tid]; sm[OFF_BE3 + tid] = be3[tid];
        }
        if (tid == 0) sm[OFF_BO] = bo[0];
    }
    __syncthreads();

    float B[9], Bi[9];
#pragma unroll
    for (int k = 0; k < 9; k++) B[k] = box[k];
    box_inverse(B, Bi);

    int lane = tid & 31;
    int wid = tid >> 5;
    float* x = sm + OFF_X + wid * (XROWS * 4);
    int n = g_count;
    int ngroups = (n + 3) >> 2;

    float mu_acsf = (float)lane * (5.f / 19.f);              // lanes 0..19
    float mu_apsf = -1.f + (float)(lane - 20) * (2.f / 9.f); // lanes 20..29
    double wacc = 0.0;

    for (int grp = wid * gridDim.x + blockIdx.x; grp < ngroups;
         grp += gridDim.x * NWARPS) {
        int base = grp * 4;
        int np = n - base; if (np > 4) np = 4;

        int p0s[4], p1s[4];
        float uxs[4], uys[4], uzs[4], ws[4];
#pragma unroll
        for (int s = 0; s < 4; s++) {
            if (s < np) {
                p0s[s] = g_p0[base + s];
                p1s[s] = g_p1[base + s];
                float4 rc = g_rec[base + s];
                float cx = rc.x + 1e-10f, cy = rc.y + 1e-10f, cz = rc.z + 1e-10f;
                float r2 = cx * cx + cy * cy + cz * cz;
                float ui = rsqrtf(r2);
                float dn = r2 * ui;
                ui = 1.f / (dn + 1e-10f);
                uxs[s] = rc.x * ui; uys[s] = rc.y * ui; uzs[s] = rc.z * ui;
                ws[s] = rc.w;
            } else { p0s[s] = 0; p1s[s] = 0; uxs[s] = uys[s] = uzs[s] = 0.f; ws[s] = 0.f; }
        }

        // zero feature rows
        {
            float4 z = make_float4(0.f, 0.f, 0.f, 0.f);
            float4* xv = (float4*)x;
            for (int i = lane; i < XROWS; i += 32) xv[i] = z;
        }
        __syncwarp();

        // parallel gather: lanes 0..23 fetch neighbors for slots {0,1} (A) / {2,3} (B);
        // lanes 24..31 fetch the 8 pair-atom centers.
        int nbA = -1, tA = 0, nbB = -1, tB = 0;
        float xA = 0.f, yA = 0.f, zA = 0.f, xB = 0.f, yB = 0.f, zB = 0.f;
        float cpx = 0.f, cpy = 0.f, cpz = 0.f; int cpt = 0;
        if (lane < 24) {
            int pr = lane / 12;
            int e = lane % 12;
            int side = e / 6, m = e % 6;
            if (pr < np) {
                int a = side ? p1s[pr] : p0s[pr];
                nbA = __ldg(topo + a * MAX_NB + m);
            }
            int prB = pr + 2;
            if (prB < np) {
                int a = side ? p1s[prB] : p0s[prB];
                nbB = __ldg(topo + a * MAX_NB + m);
            }
        } else {
            int k = lane - 24;
            int slot = k >> 1, which = k & 1;
            if (slot < np) {
                int a = which ? p1s[slot] : p0s[slot];
                cpx = __ldg(pos + 3 * a); cpy = __ldg(pos + 3 * a + 1); cpz = __ldg(pos + 3 * a + 2);
                cpt = __ldg(atype + a);
            }
        }
        if (lane < 24) {
            if (nbA >= 0) { xA = __ldg(pos + 3 * nbA); yA = __ldg(pos + 3 * nbA + 1); zA = __ldg(pos + 3 * nbA + 2); tA = __ldg(atype + nbA); }
            if (nbB >= 0) { xB = __ldg(pos + 3 * nbB); yB = __ldg(pos + 3 * nbB + 1); zB = __ldg(pos + 3 * nbB + 2); tB = __ldg(atype + nbB); }
        }
        __syncwarp();

        // contribution loop: 4 slots x 12 edges, batched by 4 with hoisted
        // shuffles + predicated math (independent chains -> ILP)
#pragma unroll
        for (int slot = 0; slot < 4; slot++) {
            if (slot >= np) break;
            int t0 = __shfl_sync(0xffffffffu, cpt, 24 + slot * 2);
            int t1 = __shfl_sync(0xffffffffu, cpt, 25 + slot * 2);
            float c0x = __shfl_sync(0xffffffffu, cpx, 24 + slot * 2);
            float c0y = __shfl_sync(0xffffffffu, cpy, 24 + slot * 2);
            float c0z = __shfl_sync(0xffffffffu, cpz, 24 + slot * 2);
            float c1x = __shfl_sync(0xffffffffu, cpx, 25 + slot * 2);
            float c1y = __shfl_sync(0xffffffffu, cpy, 25 + slot * 2);
            float c1z = __shfl_sync(0xffffffffu, cpz, 25 + slot * 2);
            float ux = uxs[slot], uy = uys[slot], uz = uzs[slot];
            float cw = ws[slot];
            int q0 = p0s[slot], q1 = p1s[slot];

            if (lane == 0) {
                x[300 * 4 + slot] = c_zidx[t0];
                x[(301 + t0) * 4 + slot] = 1.f;
                x[311 * 4 + slot] = c_zidx[t1];
                x[(312 + t1) * 4 + slot] = 1.f;
            }

#pragma unroll
            for (int b = 0; b < 3; b++) {
                // hoist all shuffles for 4 edges
                int nb4[4], te4[4];
                float ex4[4], ey4[4], ez4[4];
#pragma unroll
                for (int j = 0; j < 4; j++) {
                    int srcLane = (slot & 1) * 12 + b * 4 + j;
                    if (slot < 2) {
                        nb4[j] = __shfl_sync(0xffffffffu, nbA, srcLane);
                        ex4[j] = __shfl_sync(0xffffffffu, xA, srcLane);
                        ey4[j] = __shfl_sync(0xffffffffu, yA, srcLane);
                        ez4[j] = __shfl_sync(0xffffffffu, zA, srcLane);
                        te4[j] = __shfl_sync(0xffffffffu, tA, srcLane);
                    } else {
                        nb4[j] = __shfl_sync(0xffffffffu, nbB, srcLane);
                        ex4[j] = __shfl_sync(0xffffffffu, xB, srcLane);
                        ey4[j] = __shfl_sync(0xffffffffu, yB, srcLane);
                        ez4[j] = __shfl_sync(0xffffffffu, zB, srcLane);
                        te4[j] = __shfl_sync(0xffffffffu, tB, srcLane);
                    }
                }
                // 4 independent predicated chains
#pragma unroll
                for (int j = 0; j < 4; j++) {
                    bool valid = (nb4[j] >= 0);
                    int e = b * 4 + j;
                    int side = e / 6;
                    float cx = side ? c1x : c0x;
                    float cy = side ? c1y : c0y;
                    float cz = side ? c1z : c0z;
                    float3 d = pbc3(ex4[j] - cx, ey4[j] - cy, ez4[j] - cz, B, Bi);
                    float ddx = d.x + 1e-10f, ddy = d.y + 1e-10f, ddz = d.z + 1e-10f;
                    float r2 = ddx * ddx + ddy * ddy + ddz * ddz;
                    float rinv = rsqrtf(r2);
                    float edn = r2 * rinv;

                    if (lane < 20) {
                        float fx = edn * 0.2f;
                        if (valid && fx < 1.f) {
                            float fc = 0.5f * (__cosf(PI_F * fx) + 1.f);
                            float dm = edn - mu_acsf;
                            x[(lane * 10 + te4[j]) * 4 + slot] += 0.5f * fc * __expf(-100.f * dm * dm);
                        }
                    } else if (lane < 30) {
                        if (valid && nb4[j] != q0 && nb4[j] != q1) {
                            float sgn = side ? -1.f : 1.f;
                            float cg = (d.x * ux + d.y * uy + d.z * uz) * rinv * sgn;
                            float dm = cg - mu_apsf;
                            x[(200 + (lane - 20) * 10 + te4[j]) * 4 + slot] +=
                                0.5f * cw * __expf(-25.f * dm * dm);
                        }
                    }
                }
            }
        }
        __syncwarp();

        dense4(sm + OFF_W1, sm + OFF_B1, sm + OFF_G1, sm + OFF_BE1, x, FEAT, lane);
        dense4(sm + OFF_W2, sm + OFF_B2, sm + OFF_G2, sm + OFF_BE2, x, 64, lane);
        dense4(sm + OFF_W3, sm + OFF_B3, sm + OFF_G3, sm + OFF_BE3, x, 64, lane);

        float wo0 = sm[OFF_WO + lane], wo1 = sm[OFF_WO + lane + 32];
        float4 xv0 = *(const float4*)(x + lane * 4);
        float4 xv1 = *(const float4*)(x + (lane + 32) * 4);
        float4 v = make_float4(xv0.x * wo0 + xv1.x * wo1,
                               xv0.y * wo0 + xv1.y * wo1,
                               xv0.z * wo0 + xv1.z * wo1,
                               xv0.w * wo0 + xv1.w * wo1);
        v = allreduce4(v);
        if (lane == 0) {
            float bov = sm[OFF_BO];
            wacc += (double)((v.x + bov) * ws[0] + (v.y + bov) * ws[1]
                           + (v.z + bov) * ws[2] + (v.w + bov) * ws[3]);
        }
    }

    // finalize: block-reduce -> one global atomic; last block writes output
    if (lane == 0) s_part[wid] = wacc;
    __syncthreads();
    if (tid == 0) {
        double t = 0.0;
#pragma unroll
        for (int i = 0; i < NWARPS; i++) t += s_part[i];
        atomicAdd(&g_sum, t);
        __threadfence();
        int done = atomicAdd(&g_done, 1);
        if (done == (int)gridDim.x - 1) {
            double s = atomicAdd(&g_sum, 0.0);   // coherent read
            out[0] = (float)s;
            g_sum = 0.0;
            g_count = 0;
            g_done = 0;
        }
    }
}

// ---------------- launch ----------------
extern "C" void kernel_launch(void* const* d_in, const int* in_sizes, int n_in,
                              void* d_out, int out_size)
{
    const float* pos   = (const float*)d_in[0];
    const float* box   = (const float*)d_in[1];
    const float* valid = (const float*)d_in[2];
    const float* W1 = (const float*)d_in[3];
    const float* b1 = (const float*)d_in[4];
    const float* g1 = (const float*)d_in[5];
    const float* be1 = (const float*)d_in[6];
    const float* W2 = (const float*)d_in[7];
    const float* b2 = (const float*)d_in[8];
    const float* g2 = (const float*)d_in[9];
    const float* be2 = (const float*)d_in[10];
    const float* W3 = (const float*)d_in[11];
    const float* b3 = (const float*)d_in[12];
    const float* g3 = (const float*)d_in[13];
    const float* be3 = (const float*)d_in[14];
    const float* Wo = (const float*)d_in[15];
    const float* bo = (const float*)d_in[16];
    const int* pairs = (const int*)d_in[17];
    const int* topo  = (const int*)d_in[18];
    // d_in[19] topo_mask: redundant with topo != -1
    const int* molid = (const int*)d_in[20];
    const int* atype = (const int*)d_in[21];

    int npairs = in_sizes[17] / 3;
    if (npairs > NPAIRS_MAX) npairs = NPAIRS_MAX;

    cudaFuncSetAttribute(k_mlp, cudaFuncAttributeMaxDynamicSharedMemorySize, SMEM_BYTES);

    k_filter<<<(npairs + 255) / 256, 256>>>(pos, box, valid, pairs, molid, npairs);
    k_mlp<<<MLP_BLOCKS, THREADS, SMEM_BYTES>>>(pos, box, topo, atype,
        W1, b1, g1, be1, W2, b2, g2, be2, W3, b3, g3, be3, Wo, bo,
        (float*)d_out);
}